// round 10
// baseline (speedup 1.0000x reference)
#include <cuda_runtime.h>

// ---------------- problem dims ----------------
#define B   32
#define C   128      // image channels / embed dim
#define S   1024     // 32*32 spatial
#define C2  256      // conv1 out channels
#define NB  100
#define LAM 0.7f

// ---------------- scratch (device globals; no allocs) ----------------
__device__ float g_c[2*B*C2*16*16];   // relu(conv1) for xa/xb   (16.8 MB)
__device__ float g_mean[2*B*C];       // spatial mean of raw x
__device__ float g_flmean[2*B*C];     // spatial mean of channel-normalized x
__device__ float g_feat[2*B*C];       // spatial SUM of relu(conv2) (/256 later)
__device__ float g_Pn[NB*C];          // 3 * l2norm(proxies)
__device__ float g_pn2[NB];           // ||Pn_j||^2
__device__ float g_ssep[2*512];       // decode SSE partials per block
__device__ float g_rowloss[4*B*2];    // [-logp(la), -logp(lb)] per row per feat-set

__device__ __forceinline__ float warp_sum(float v){
    #pragma unroll
    for (int o = 16; o; o >>= 1) v += __shfl_down_sync(0xffffffffu, v, o);
    return v;
}

// ---- f32x2 packed math helpers ----
__device__ __forceinline__ unsigned long long pack2(float v){
    unsigned long long r; unsigned u = __float_as_uint(v);
    asm("mov.b64 %0, {%1, %1};" : "=l"(r) : "r"(u));
    return r;
}
__device__ __forceinline__ void ffma2(unsigned long long& d, unsigned long long a, unsigned long long b){
    asm("fma.rn.f32x2 %0, %1, %2, %0;" : "+l"(d) : "l"(a), "l"(b));
}
__device__ __forceinline__ float lo2(unsigned long long v){ return __uint_as_float((unsigned)v); }
__device__ __forceinline__ float hi2(unsigned long long v){ return __uint_as_float((unsigned)(v >> 32)); }

// ---------------- fused per-pixel channel norms + raw/normalized spatial means ----------------
__global__ __launch_bounds__(256) void normmeans_kernel(const float* __restrict__ xa,
                                                        const float* __restrict__ xb){
    int t = blockIdx.y, b = blockIdx.x;
    const float* x = (t ? xb : xa) + (size_t)b * C * S;
    __shared__ float s_inv[S];   // 4KB
    int tid = threadIdx.x;
    #pragma unroll
    for (int k = 0; k < 4; ++k) {
        int s = k*256 + tid;
        float ss = 0.f;
        #pragma unroll 4
        for (int c = 0; c < C; ++c) { float v = x[(size_t)c*S + s]; ss += v*v; }
        s_inv[s] = 1.0f / fmaxf(sqrtf(ss), 1e-12f);
    }
    __syncthreads();
    int w = tid >> 5, l = tid & 31;
    for (int j = 0; j < 16; ++j) {
        int c = w*16 + j;
        const float* xc = x + (size_t)c*S;
        float s1 = 0.f, s2 = 0.f;
        #pragma unroll 4
        for (int m = 0; m < 32; ++m) {
            float v = xc[m*32 + l];
            s1 += v; s2 += v * s_inv[m*32 + l];
        }
        s1 = warp_sum(s1); s2 = warp_sum(s2);
        if (l == 0) {
            g_mean  [(t*B + b)*C + c] = s1 * (1.0f / S);
            g_flmean[(t*B + b)*C + c] = s2 * (1.0f / S);
        }
    }
}

// ---------------- conv1: 128->256, k3 s2, SAME pad (0,1), + ReLU ----------------
__global__ __launch_bounds__(256) void conv1_kernel(const float* __restrict__ xa,
                                                    const float* __restrict__ xb,
                                                    const float* __restrict__ W){
    int t = blockIdx.z, b = blockIdx.y, oc0 = blockIdx.x * 32;
    const float* x = (t ? xb : xa) + (size_t)b * C * S;
    __shared__ __align__(16) float s_pp[2][4*33*24];  // [parity][ci*792 + y*24 + e]
    __shared__ __align__(16) float s_w[36*32];        // [(ci*9+k)*32 + oc_local]
    int tid = threadIdx.x;
    unsigned long long a01[8], a23[8];
    #pragma unroll
    for (int p = 0; p < 8; ++p) { a01[p] = 0ull; a23[p] = 0ull; }
    int pxt = tid & 31, oct = tid >> 5;
    int x0 = pxt & 15, y0 = pxt >> 4;

    for (int ch = 0; ch < 32; ++ch) {
        int ci0 = ch * 4;
        for (int i = tid; i < 1152; i += 256) {
            int oci = i & 31, r = i >> 5;   // r = ci*9+k
            s_w[i] = W[(size_t)(oc0 + oci) * (C*9) + ci0*9 + r];
        }
        for (int i = tid; i < 4356; i += 256) {
            int ci = i / 1089, r = i - ci * 1089;
            int y = r / 33, xx = r - y * 33;
            float v = 0.f;
            if (y < 32 && xx < 32) v = x[(size_t)(ci0 + ci) * S + y*32 + xx];
            s_pp[xx & 1][ci*792 + y*24 + (xx >> 1)] = v;
        }
        __syncthreads();
        #pragma unroll 1
        for (int ci = 0; ci < 4; ++ci) {
            #pragma unroll
            for (int ky = 0; ky < 3; ++ky)
            #pragma unroll
            for (int kx = 0; kx < 3; ++kx) {
                ulonglong2 w = *reinterpret_cast<const ulonglong2*>(
                    &s_w[(ci*9 + ky*3 + kx)*32 + oct*4]);
                const float* ip = &s_pp[kx & 1][ci*792 + (2*y0 + ky)*24 + x0 + (kx >> 1)];
                #pragma unroll
                for (int pi = 0; pi < 8; ++pi) {
                    unsigned long long iv = pack2(ip[pi*96]);   // 4 rows * 24
                    ffma2(a01[pi], iv, w.x);
                    ffma2(a23[pi], iv, w.y);
                }
            }
        }
        __syncthreads();
    }
    float* cb = g_c + (size_t)(t*B + b) * C2 * 256;
    #pragma unroll
    for (int pi = 0; pi < 8; ++pi) {
        int y = y0 + 2*pi;
        int base = y*16 + x0, oc = oc0 + oct*4;
        cb[(size_t)(oc + 0)*256 + base] = fmaxf(lo2(a01[pi]), 0.f);
        cb[(size_t)(oc + 1)*256 + base] = fmaxf(hi2(a01[pi]), 0.f);
        cb[(size_t)(oc + 2)*256 + base] = fmaxf(lo2(a23[pi]), 0.f);
        cb[(size_t)(oc + 3)*256 + base] = fmaxf(hi2(a23[pi]), 0.f);
    }
}

// ---------------- conv2: 256->128, k3 s1, pad (1,1), +ReLU, fused spatial sum ----------------
__global__ __launch_bounds__(256) void conv2_kernel(const float* __restrict__ W){
    int t = blockIdx.z, b = blockIdx.y, oc0 = blockIdx.x * 32;
    const float* cin = g_c + (size_t)(t*B + b) * C2 * 256;
    __shared__ __align__(16) float s_in[8*18*48];   // [ci*864 + yy*48 + xx]
    __shared__ __align__(16) float s_w[72*32];      // [(ci*9+k)*32 + oc_local]
    __shared__ float s_red[32*32];
    int tid = threadIdx.x;
    unsigned long long a01[8], a23[8];
    #pragma unroll
    for (int p = 0; p < 8; ++p) { a01[p] = 0ull; a23[p] = 0ull; }
    int pxt = tid & 31, oct = tid >> 5;
    int x0 = pxt & 15, y0 = pxt >> 4;

    for (int ch = 0; ch < 32; ++ch) {
        int ci0 = ch * 8;
        for (int i = tid; i < 2304; i += 256) {
            int oci = i & 31, r = i >> 5;
            s_w[i] = W[(size_t)(oc0 + oci) * (C2*9) + ci0*9 + r];
        }
        for (int i = tid; i < 2592; i += 256) {
            int cii = i / 324, r = i - cii * 324;
            int yy = r / 18, xx = r - yy * 18;
            int y = yy - 1, xq = xx - 1;
            float v = 0.f;
            if (y >= 0 && y < 16 && xq >= 0 && xq < 16)
                v = cin[(size_t)(ci0 + cii)*256 + y*16 + xq];
            s_in[cii*864 + yy*48 + xx] = v;
        }
        __syncthreads();
        #pragma unroll 1
        for (int ci = 0; ci < 8; ++ci) {
            #pragma unroll
            for (int ky = 0; ky < 3; ++ky)
            #pragma unroll
            for (int kx = 0; kx < 3; ++kx) {
                ulonglong2 w = *reinterpret_cast<const ulonglong2*>(
                    &s_w[(ci*9 + ky*3 + kx)*32 + oct*4]);
                const float* ip = &s_in[ci*864 + (y0 + ky)*48 + x0 + kx];
                #pragma unroll
                for (int pi = 0; pi < 8; ++pi) {
                    unsigned long long iv = pack2(ip[pi*96]);   // 2 rows * 48
                    ffma2(a01[pi], iv, w.x);
                    ffma2(a23[pi], iv, w.y);
                }
            }
        }
        __syncthreads();
    }
    #pragma unroll
    for (int j = 0; j < 4; ++j) {
        float s = 0.f;
        #pragma unroll
        for (int pi = 0; pi < 8; ++pi) {
            float v = (j == 0) ? lo2(a01[pi]) : (j == 1) ? hi2(a01[pi])
                    : (j == 2) ? lo2(a23[pi]) : hi2(a23[pi]);
            s += fmaxf(v, 0.f);
        }
        s_red[(oct*4 + j)*32 + pxt] = s;
    }
    __syncthreads();
    if (tid < 32) {
        float tot = 0.f;
        for (int p = 0; p < 32; ++p) tot += s_red[tid*32 + p];
        g_feat[(t*B + b)*C + oc0 + tid] = tot;
    }
}

// ---------------- decode (conv_transpose s2, SAME pad (2,1)) as 4 polyphase classes, one kernel ----------------
template<int PY, int PX>
__device__ __forceinline__ void decode_impl(
        float* s_c, float* s_w, float* sred,
        int t, int b, int oc0, int ocg,
        const float* __restrict__ xa, const float* __restrict__ xb,
        const float* __restrict__ W)
{
    constexpr int TY = PY ? 1 : 2, TX = PX ? 1 : 2, NT = TY * TX;
    const float* cin = g_c + (size_t)(t*B + b) * C2 * 256;
    const float* x = (t ? xb : xa) + (size_t)b * C * S;
    int tid = threadIdx.x;
    unsigned long long a01[8], a23[8];
    #pragma unroll
    for (int p = 0; p < 8; ++p) { a01[p] = 0ull; a23[p] = 0ull; }
    int pxt = tid & 31, oct = tid >> 5;
    int x0 = pxt & 15, y0 = pxt >> 4;

    for (int ch = 0; ch < 32; ++ch) {
        int ci0 = ch * 8;
        for (int i = tid; i < 8*NT*32; i += 256) {
            int oci = i & 31, q = i >> 5;       // q = cii*NT + tt
            int cii = q / NT, tt = q - cii*NT;
            int ta = tt / TX, tb = tt - ta*TX;
            int ky = PY ? 1 : 2*ta, kx = PX ? 1 : 2*tb;
            s_w[i] = W[((size_t)(oc0 + oci)*C2 + ci0 + cii)*9 + ky*3 + kx];
        }
        for (int i = tid; i < 2312; i += 256) {
            int cii = i / 289, r = i - cii*289;
            int yy = r / 17, xx = r - yy*17;
            int y = yy - 1, xq = xx - 1;
            float v = 0.f;
            if (y >= 0 && y < 16 && xq >= 0 && xq < 16)
                v = cin[(size_t)(ci0 + cii)*256 + y*16 + xq];
            s_c[cii*816 + yy*48 + xx] = v;      // 17 rows * stride 48
        }
        __syncthreads();
        #pragma unroll 1
        for (int ci = 0; ci < 8; ++ci) {
            #pragma unroll
            for (int tt = 0; tt < NT; ++tt) {
                int ta = tt / TX, tb = tt - ta*TX;
                ulonglong2 w = *reinterpret_cast<const ulonglong2*>(
                    &s_w[(ci*NT + tt)*32 + oct*4]);
                int row0 = PY ? (y0 + 1) : (y0 + ta);
                int col  = PX ? (x0 + 1) : (x0 + tb);
                const float* ip = &s_c[ci*816 + row0*48 + col];
                #pragma unroll
                for (int pi = 0; pi < 8; ++pi) {
                    unsigned long long iv = pack2(ip[pi*96]);   // 2 rows * 48
                    ffma2(a01[pi], iv, w.x);
                    ffma2(a23[pi], iv, w.y);
                }
            }
        }
        __syncthreads();
    }
    float sse = 0.f;
    #pragma unroll
    for (int pi = 0; pi < 8; ++pi) {
        int yo = 2*(y0 + 2*pi) + PY, xo = 2*x0 + PX;
        int oc = oc0 + oct*4;
        float d0 = lo2(a01[pi]) - x[(size_t)(oc+0)*S + yo*32 + xo];
        float d1 = hi2(a01[pi]) - x[(size_t)(oc+1)*S + yo*32 + xo];
        float d2 = lo2(a23[pi]) - x[(size_t)(oc+2)*S + yo*32 + xo];
        float d3 = hi2(a23[pi]) - x[(size_t)(oc+3)*S + yo*32 + xo];
        sse += d0*d0 + d1*d1 + d2*d2 + d3*d3;
    }
    sse = warp_sum(sse);
    if ((tid & 31) == 0) sred[tid >> 5] = sse;
    __syncthreads();
    if (tid == 0) {
        float tot = 0.f;
        for (int i = 0; i < 8; ++i) tot += sred[i];
        int cls = PY*2 + PX;
        g_ssep[t*512 + (cls*4 + ocg)*32 + b] = tot;
    }
}

__global__ __launch_bounds__(256) void decode_all_kernel(const float* __restrict__ xa,
                                                         const float* __restrict__ xb,
                                                         const float* __restrict__ W){
    __shared__ __align__(16) float s_c[8*17*48];   // 26.1 KB
    __shared__ __align__(16) float s_w[8*4*32];    // max NT=4
    __shared__ float sred[8];
    int cls = blockIdx.x >> 2, ocg = blockIdx.x & 3;
    int t = blockIdx.z, b = blockIdx.y, oc0 = ocg * 32;
    switch (cls) {
        case 0: decode_impl<0,0>(s_c, s_w, sred, t, b, oc0, ocg, xa, xb, W); break;
        case 1: decode_impl<0,1>(s_c, s_w, sred, t, b, oc0, ocg, xa, xb, W); break;
        case 2: decode_impl<1,0>(s_c, s_w, sred, t, b, oc0, ocg, xa, xb, W); break;
        default: decode_impl<1,1>(s_c, s_w, sred, t, b, oc0, ocg, xa, xb, W); break;
    }
}

// ---------------- proxies: Pn = 3*l2norm(P), pn2 ----------------
__global__ void proxy_kernel(const float* __restrict__ P){
    int j = blockIdx.x, c = threadIdx.x;
    float p = P[j*C + c];
    float ss = warp_sum(p * p);
    __shared__ float r[4];
    __shared__ float s_inv;
    if ((c & 31) == 0) r[c >> 5] = ss;
    __syncthreads();
    if (c == 0) {
        float tot = r[0] + r[1] + r[2] + r[3];
        float inv = 1.0f / fmaxf(sqrtf(tot), 1e-12f);
        s_inv = inv;
        g_pn2[j] = 9.0f * tot * inv * inv;
    }
    __syncthreads();
    g_Pn[j*C + c] = 3.0f * p * s_inv;
}

// ---------------- per-row proxy metric loss for 4 feat sets ----------------
__global__ void rowloss_kernel(const int* __restrict__ la, const int* __restrict__ lb){
    int i = blockIdx.x, set = blockIdx.y;
    int c = threadIdx.x;                  // 128 threads
    __shared__ float sX[C];
    __shared__ float sD[NB];
    __shared__ float rbuf[4];
    __shared__ float s_sc[2];
    float v;
    if      (set == 0) v = g_feat[(0*B + i)*C + c] * (1.0f/256.f);
    else if (set == 1) v = g_feat[(1*B + i)*C + c] * (1.0f/256.f);
    else if (set == 2) v = LAM*g_mean[(0*B + i)*C + c] + (1.0f-LAM)*g_flmean[(1*B + i)*C + c];
    else               v = LAM*g_mean[(1*B + i)*C + c] + (1.0f-LAM)*g_flmean[(0*B + i)*C + c];
    sX[c] = v;
    float ss = warp_sum(v * v);
    int w = c >> 5, l = c & 31;
    if (l == 0) rbuf[w] = ss;
    __syncthreads();
    if (c == 0) {
        float tot = rbuf[0] + rbuf[1] + rbuf[2] + rbuf[3];
        float inv = 1.0f / fmaxf(sqrtf(tot), 1e-12f);
        s_sc[0] = inv;
        s_sc[1] = 9.0f * tot * inv * inv;
    }
    __syncthreads();
    float inv = s_sc[0], xn2 = s_sc[1];
    for (int j = w; j < NB; j += 4) {
        const float* pn = g_Pn + j*C;
        float d = sX[l]*pn[l] + sX[l+32]*pn[l+32] + sX[l+64]*pn[l+64] + sX[l+96]*pn[l+96];
        d = warp_sum(d);
        if (l == 0) sD[j] = xn2 + g_pn2[j] - 6.0f * inv * d;
    }
    __syncthreads();
    // log-sum-exp over -D
    float m = (c < NB) ? -sD[c] : -3.0e38f;
    float mm = m;
    #pragma unroll
    for (int o = 16; o; o >>= 1) mm = fmaxf(mm, __shfl_down_sync(0xffffffffu, mm, o));
    if (l == 0) rbuf[w] = mm;
    __syncthreads();
    if (c == 0) s_sc[0] = fmaxf(fmaxf(rbuf[0], rbuf[1]), fmaxf(rbuf[2], rbuf[3]));
    __syncthreads();
    float M = s_sc[0];
    float e = (c < NB) ? expf(m - M) : 0.f;
    e = warp_sum(e);
    if (l == 0) rbuf[w] = e;
    __syncthreads();
    if (c == 0) {
        float sum = rbuf[0] + rbuf[1] + rbuf[2] + rbuf[3];
        float lse = M + logf(sum);
        int ila = la[i], ilb = lb[i];
        g_rowloss[(set*B + i)*2 + 0] = sD[ila] + lse;   // -logp[i, la_i]
        g_rowloss[(set*B + i)*2 + 1] = sD[ilb] + lse;   // -logp[i, lb_i]
    }
}

// ---------------- final combine -> 7 outputs ----------------
__global__ void final_kernel(float* __restrict__ out){
    int tid = threadIdx.x;  // 256
    float sa = g_ssep[tid]       + g_ssep[tid + 256];
    float sb = g_ssep[512 + tid] + g_ssep[768 + tid];
    __shared__ float ra[8], rb[8];
    sa = warp_sum(sa); sb = warp_sum(sb);
    if ((tid & 31) == 0) { ra[tid >> 5] = sa; rb[tid >> 5] = sb; }
    __syncthreads();
    if (tid == 0) {
        float ssea = 0.f, sseb = 0.f;
        for (int i = 0; i < 8; ++i) { ssea += ra[i]; sseb += rb[i]; }
        float lxa = ssea * (1.0f / ((float)B * C * S));
        float lxb = sseb * (1.0f / ((float)B * C * S));
        float m[4][2] = {};
        for (int s = 0; s < 4; ++s)
            for (int i = 0; i < B; ++i) {
                m[s][0] += g_rowloss[(s*B + i)*2 + 0];
                m[s][1] += g_rowloss[(s*B + i)*2 + 1];
            }
        float lca = m[0][0] / B;
        float lcb = m[1][1] / B;
        float lma = LAM*(m[2][0]/B) + (1.0f-LAM)*(m[2][1]/B);
        float lmb = LAM*(m[3][1]/B) + (1.0f-LAM)*(m[3][0]/B);
        out[1] = lxa; out[2] = lxb; out[3] = lca; out[4] = lcb; out[5] = lma; out[6] = lmb;
        out[0] = lxa + lxb + lca + lcb + lma + lmb;
    }
}

// ---------------- launch ----------------
extern "C" void kernel_launch(void* const* d_in, const int* in_sizes, int n_in,
                              void* d_out, int out_size){
    (void)in_sizes; (void)n_in; (void)out_size;
    const float* xa    = (const float*)d_in[0];
    const float* xb    = (const float*)d_in[1];
    const int*   la    = (const int*)  d_in[2];
    const int*   lb    = (const int*)  d_in[3];
    const float* prox  = (const float*)d_in[4];
    const float* Wenc  = (const float*)d_in[5];
    const float* Wfeat = (const float*)d_in[6];
    const float* Wdec  = (const float*)d_in[7];
    float* out = (float*)d_out;

    normmeans_kernel <<<dim3(B, 2),     256>>>(xa, xb);
    conv1_kernel     <<<dim3(8,  B, 2), 256>>>(xa, xb, Wenc);
    conv2_kernel     <<<dim3(4,  B, 2), 256>>>(Wfeat);
    decode_all_kernel<<<dim3(16, B, 2), 256>>>(xa, xb, Wdec);
    proxy_kernel     <<<NB, 128>>>(prox);
    rowloss_kernel   <<<dim3(B, 4), 128>>>(la, lb);
    final_kernel     <<<1, 256>>>(out);
}